// round 2
// baseline (speedup 1.0000x reference)
#include <cuda_runtime.h>
#include <float.h>

#define D    256
#define NE   8192
#define TOK  32768
#define BM   64
#define BN   64
#define PAD  258   // row stride in floats: conflict-free strided LDS, 8B-aligned float2

// Scratch (device globals — no allocations allowed)
__device__ float g_e2[NE];
__device__ float g_z2[TOK];
__device__ int   g_idx[TOK];
__device__ float g_partial[TOK];

// ---------------------------------------------------------------------------
// Row sum-of-squares: one warp per row of a [rows, 256] matrix.
// ---------------------------------------------------------------------------
__global__ void rowsq_emb(const float* __restrict__ emb) {
    int row  = blockIdx.x * 8 + (threadIdx.x >> 5);
    int lane = threadIdx.x & 31;
    const float4* e = reinterpret_cast<const float4*>(emb + (size_t)row * D);
    float s = 0.f;
#pragma unroll
    for (int c = 0; c < 2; c++) {
        float4 v = e[lane + 32 * c];
        s += v.x * v.x + v.y * v.y + v.z * v.z + v.w * v.w;
    }
#pragma unroll
    for (int o = 16; o; o >>= 1) s += __shfl_down_sync(0xffffffffu, s, o);
    if (lane == 0) g_e2[row] = s;
}

__global__ void rowsq_z(const float* __restrict__ z) {
    int row  = blockIdx.x * 8 + (threadIdx.x >> 5);
    int lane = threadIdx.x & 31;
    const float4* e = reinterpret_cast<const float4*>(z + (size_t)row * D);
    float s = 0.f;
#pragma unroll
    for (int c = 0; c < 2; c++) {
        float4 v = e[lane + 32 * c];
        s += v.x * v.x + v.y * v.y + v.z * v.z + v.w * v.w;
    }
#pragma unroll
    for (int o = 16; o; o >>= 1) s += __shfl_down_sync(0xffffffffu, s, o);
    if (lane == 0) g_z2[row] = s;
}

// ---------------------------------------------------------------------------
// Fused GEMM + argmin. Block = 64 tokens; scans all 8192 codes in 64-chunks.
// Score replicates XLA fp32 quantization: s = fl(fl(z2 - 2*dot) + e2).
// ---------------------------------------------------------------------------
__global__ void __launch_bounds__(256, 1)
vq_argmin(const float* __restrict__ z, const float* __restrict__ emb,
          float* __restrict__ out_idx) {
    extern __shared__ float sm[];
    float* As  = sm;                  // BM * PAD
    float* Bs  = sm + BM * PAD;       // BN * PAD
    float* e2s = sm + 2 * BM * PAD;   // BN

    const int tid = threadIdx.x;
    const int tx  = tid & 15;         // code (N) dimension
    const int ty  = tid >> 4;         // token (M) dimension
    const int m0  = blockIdx.x * BM;

    // Load z tile [64,256] once (coalesced float4 from gmem)
#pragma unroll
    for (int i = 0; i < 16; i++) {
        int f4 = tid + i * 256;
        int r = f4 >> 6, c4 = f4 & 63;
        float4 v = reinterpret_cast<const float4*>(z + (size_t)(m0 + r) * D)[c4];
        float* dst = As + r * PAD + c4 * 4;
        dst[0] = v.x; dst[1] = v.y; dst[2] = v.z; dst[3] = v.w;
    }

    float z2[4];
#pragma unroll
    for (int i = 0; i < 4; i++) z2[i] = g_z2[m0 + ty + 16 * i];

    float minv[4]; int mini[4];
#pragma unroll
    for (int i = 0; i < 4; i++) { minv[i] = FLT_MAX; mini[i] = 0; }

    for (int n0 = 0; n0 < NE; n0 += BN) {
        __syncthreads();  // previous-iter readers done before overwriting Bs
#pragma unroll
        for (int i = 0; i < 16; i++) {
            int f4 = tid + i * 256;
            int r = f4 >> 6, c4 = f4 & 63;
            float4 v = reinterpret_cast<const float4*>(emb + (size_t)(n0 + r) * D)[c4];
            float* dst = Bs + r * PAD + c4 * 4;
            dst[0] = v.x; dst[1] = v.y; dst[2] = v.z; dst[3] = v.w;
        }
        if (tid < BN) e2s[tid] = g_e2[n0 + tid];
        __syncthreads();

        float acc[4][4];
#pragma unroll
        for (int i = 0; i < 4; i++)
#pragma unroll
            for (int j = 0; j < 4; j++) acc[i][j] = 0.f;

#pragma unroll 4
        for (int k = 0; k < D; k += 2) {
            float2 a[4], b[4];
#pragma unroll
            for (int i = 0; i < 4; i++)
                a[i] = *reinterpret_cast<const float2*>(As + (ty + 16 * i) * PAD + k);
#pragma unroll
            for (int j = 0; j < 4; j++)
                b[j] = *reinterpret_cast<const float2*>(Bs + (tx + 16 * j) * PAD + k);
#pragma unroll
            for (int i = 0; i < 4; i++)
#pragma unroll
                for (int j = 0; j < 4; j++)
                    acc[i][j] += a[i].x * b[j].x + a[i].y * b[j].y;
        }

#pragma unroll
        for (int j = 0; j < 4; j++) {
            int   n  = n0 + tx + 16 * j;        // ascending in j and n0
            float e2 = e2s[tx + 16 * j];
#pragma unroll
            for (int i = 0; i < 4; i++) {
                float v = z2[i] - 2.0f * acc[i][j];  // fl(z2 - 2 dot)
                float s = v + e2;                    // fl(... + e2): XLA-style quantized
                if (s < minv[i]) { minv[i] = s; mini[i] = n; }  // first-min tie-break
            }
        }
    }

    // Cross-thread (tx) reduction per token row, lexicographic (val, idx)
    __syncthreads();
    float* rv = sm;                     // 64*16 floats (reuse As space)
    int*   ri = (int*)(sm + 64 * 16);   // 64*16 ints
#pragma unroll
    for (int i = 0; i < 4; i++) {
        rv[(ty + 16 * i) * 16 + tx] = minv[i];
        ri[(ty + 16 * i) * 16 + tx] = mini[i];
    }
    __syncthreads();
    if (tid < BM) {
        float best = rv[tid * 16]; int bi = ri[tid * 16];
#pragma unroll
        for (int t = 1; t < 16; t++) {
            float v = rv[tid * 16 + t]; int n = ri[tid * 16 + t];
            if (v < best || (v == best && n < bi)) { best = v; bi = n; }
        }
        g_idx[m0 + tid]   = bi;
        out_idx[m0 + tid] = (float)bi;
    }
}

// ---------------------------------------------------------------------------
// Gather z_q, straight-through output fl(z + fl(z_q - z)), per-token loss partial
// ---------------------------------------------------------------------------
__global__ void gather_loss(const float* __restrict__ z, const float* __restrict__ emb,
                            float* __restrict__ out_zq) {
    int t = blockIdx.x;
    int d = threadIdx.x;
    int e = g_idx[t];
    float zq = emb[(size_t)e * D + d];
    float zz = z[(size_t)t * D + d];
    float diff = zq - zz;                       // fl(z_q - z)
    out_zq[(size_t)t * D + d] = zz + diff;      // fl(z + fl(z_q - z))  (STE value)
    float sq = diff * diff;
    __shared__ float red[8];
#pragma unroll
    for (int o = 16; o; o >>= 1) sq += __shfl_down_sync(0xffffffffu, sq, o);
    if ((d & 31) == 0) red[d >> 5] = sq;
    __syncthreads();
    if (d < 8) {
        float s = red[d];
#pragma unroll
        for (int o = 4; o; o >>= 1) s += __shfl_down_sync(0xffu, s, o);
        if (d == 0) g_partial[t] = s;
    }
}

__global__ void finalize_loss(float* __restrict__ out_loss) {
    __shared__ double red[8];
    double s = 0.0;
    for (int i = threadIdx.x; i < TOK; i += 256) s += (double)g_partial[i];
#pragma unroll
    for (int o = 16; o; o >>= 1) s += __shfl_down_sync(0xffffffffu, s, o);
    if ((threadIdx.x & 31) == 0) red[threadIdx.x >> 5] = s;
    __syncthreads();
    if (threadIdx.x < 8) {
        double v = red[threadIdx.x];
#pragma unroll
        for (int o = 4; o; o >>= 1) v += __shfl_down_sync(0xffu, v, o);
        if (threadIdx.x == 0) {
            double mean = v / (double)((size_t)TOK * D);
            out_loss[0] = (float)(1.25 * mean);  // (1 + beta) * mean((z_q - z)^2)
        }
    }
}

// ---------------------------------------------------------------------------
extern "C" void kernel_launch(void* const* d_in, const int* in_sizes, int n_in,
                              void* d_out, int out_size) {
    const float* z   = (const float*)d_in[0];   // [8,4096,256] -> [32768,256]
    const float* emb = (const float*)d_in[1];   // [8192,256]

    float* out      = (float*)d_out;
    float* out_zq   = out;                       // TOK*D elements
    float* out_loss = out + (size_t)TOK * D;     // 1 element
    float* out_idx  = out + (size_t)TOK * D + 1; // TOK elements

    const int smem_bytes = (2 * BM * PAD + BN) * (int)sizeof(float);  // ~132 KB
    cudaFuncSetAttribute(vq_argmin, cudaFuncAttributeMaxDynamicSharedMemorySize,
                         smem_bytes);

    rowsq_emb<<<NE / 8, 256>>>(emb);
    rowsq_z<<<TOK / 8, 256>>>(z);
    vq_argmin<<<TOK / BM, 256, smem_bytes>>>(z, emb, out_idx);
    gather_loss<<<TOK, 256>>>(z, emb, out_zq);
    finalize_loss<<<1, 256>>>(out_loss);
}